// round 2
// baseline (speedup 1.0000x reference)
#include <cuda_runtime.h>
#include <cstdint>

#define B_  4
#define N_  8192
#define K_  16
#define D_  64
#define M_  (B_ * N_)   // 32768 points

// ---------------- scratch (static device arrays; no allocation) ----------------
__device__ float g_q[M_ * D_];
__device__ float g_k[M_ * D_];
__device__ float g_v[M_ * D_];

// ---------------- f32x2 packed-FMA helpers ----------------
__device__ __forceinline__ unsigned long long pack2(float x, float y) {
    unsigned long long r;
    asm("mov.b64 %0, {%1, %2};" : "=l"(r) : "f"(x), "f"(y));
    return r;
}
__device__ __forceinline__ void fma2(unsigned long long& d, unsigned long long a, unsigned long long b) {
    asm("fma.rn.f32x2 %0, %1, %2, %0;" : "+l"(d) : "l"(a), "l"(b));
}
__device__ __forceinline__ float2 unpk(unsigned long long v) {
    float x, y;
    asm("mov.b64 {%0, %1}, %2;" : "=f"(x), "=f"(y) : "l"(v));
    return make_float2(x, y);
}

// rank-1 update: 4 rows (a0..a3) x 4 cols (b = two packed f32x2 pairs)
__device__ __forceinline__ void rank1(float a0, float a1, float a2, float a3,
                                      ulonglong2 b, unsigned long long acc[4][2]) {
    unsigned long long t;
    t = pack2(a0, a0); fma2(acc[0][0], t, b.x); fma2(acc[0][1], t, b.y);
    t = pack2(a1, a1); fma2(acc[1][0], t, b.x); fma2(acc[1][1], t, b.y);
    t = pack2(a2, a2); fma2(acc[2][0], t, b.x); fma2(acc[2][1], t, b.y);
    t = pack2(a3, a3); fma2(acc[3][0], t, b.x); fma2(acc[3][1], t, b.y);
}

// C(64x64) = A(64x64, smem, stride 68) @ W(64x64, smem, stride 68)
// thread owns rows r0..r0+3, cols c0..c0+3 (accumulated as packed f32x2 pairs)
__device__ __forceinline__ void gemm64(const float* As, const float* Ws,
                                       int r0, int c0, unsigned long long acc[4][2]) {
#pragma unroll
    for (int i = 0; i < 4; i++) { acc[i][0] = 0ULL; acc[i][1] = 0ULL; }
#pragma unroll
    for (int k4 = 0; k4 < 16; ++k4) {
        float4 a0 = *reinterpret_cast<const float4*>(As + (r0 + 0) * 68 + k4 * 4);
        float4 a1 = *reinterpret_cast<const float4*>(As + (r0 + 1) * 68 + k4 * 4);
        float4 a2 = *reinterpret_cast<const float4*>(As + (r0 + 2) * 68 + k4 * 4);
        float4 a3 = *reinterpret_cast<const float4*>(As + (r0 + 3) * 68 + k4 * 4);
        ulonglong2 b0 = *reinterpret_cast<const ulonglong2*>(Ws + (k4 * 4 + 0) * 68 + c0);
        ulonglong2 b1 = *reinterpret_cast<const ulonglong2*>(Ws + (k4 * 4 + 1) * 68 + c0);
        ulonglong2 b2 = *reinterpret_cast<const ulonglong2*>(Ws + (k4 * 4 + 2) * 68 + c0);
        ulonglong2 b3 = *reinterpret_cast<const ulonglong2*>(Ws + (k4 * 4 + 3) * 68 + c0);
        rank1(a0.x, a1.x, a2.x, a3.x, b0, acc);
        rank1(a0.y, a1.y, a2.y, a3.y, b1, acc);
        rank1(a0.z, a1.z, a2.z, a3.z, b2, acc);
        rank1(a0.w, a1.w, a2.w, a3.w, b3, acc);
    }
}

// cooperative 64x64 weight load global -> smem (stride 68), 256 threads
__device__ __forceinline__ void loadW(float* dst, const float* __restrict__ src, int tid) {
#pragma unroll
    for (int e = tid; e < 1024; e += 256) {
        int row = e >> 4, c4 = e & 15;
        float4 v = *reinterpret_cast<const float4*>(src + row * 64 + c4 * 4);
        *reinterpret_cast<float4*>(dst + row * 68 + c4 * 4) = v;
    }
}

// =========================================================================
// Kernel 1: x = features@fc1 + b ; q/k/v = x@{wq,wk,wv}
// =========================================================================
__global__ __launch_bounds__(256)
void k1_proj(const float* __restrict__ features,
             const float* __restrict__ fc1w, const float* __restrict__ fc1b,
             const float* __restrict__ wq, const float* __restrict__ wk,
             const float* __restrict__ wv) {
    __shared__ float Fs[64 * 68];
    __shared__ float Ws[64 * 68];

    const int tid = threadIdx.x;
    const int m0 = blockIdx.x * 64;
    const int tr = tid >> 4, tc = tid & 15;
    const int r0 = tr * 4, c0 = tc * 4;

    // load features tile + fc1
#pragma unroll
    for (int e = tid; e < 1024; e += 256) {
        int row = e >> 4, c4 = e & 15;
        float4 v = *reinterpret_cast<const float4*>(features + (m0 + row) * 64 + c4 * 4);
        *reinterpret_cast<float4*>(Fs + row * 68 + c4 * 4) = v;
    }
    loadW(Ws, fc1w, tid);
    __syncthreads();

    unsigned long long acc[4][2];
    gemm64(Fs, Ws, r0, c0, acc);
    __syncthreads();   // reads of Fs/Ws done everywhere

    // x = acc + fc1b  -> overwrite Fs ; load wq
#pragma unroll
    for (int i = 0; i < 4; i++) {
        float2 u0 = unpk(acc[i][0]), u1 = unpk(acc[i][1]);
        Fs[(r0 + i) * 68 + c0 + 0] = u0.x + __ldg(&fc1b[c0 + 0]);
        Fs[(r0 + i) * 68 + c0 + 1] = u0.y + __ldg(&fc1b[c0 + 1]);
        Fs[(r0 + i) * 68 + c0 + 2] = u1.x + __ldg(&fc1b[c0 + 2]);
        Fs[(r0 + i) * 68 + c0 + 3] = u1.y + __ldg(&fc1b[c0 + 3]);
    }
    loadW(Ws, wq, tid);
    __syncthreads();

    gemm64(Fs, Ws, r0, c0, acc);
#pragma unroll
    for (int i = 0; i < 4; i++) {
        float2 u0 = unpk(acc[i][0]), u1 = unpk(acc[i][1]);
        *reinterpret_cast<float4*>(g_q + (m0 + r0 + i) * 64 + c0) =
            make_float4(u0.x, u0.y, u1.x, u1.y);
    }
    __syncthreads();
    loadW(Ws, wk, tid);
    __syncthreads();

    gemm64(Fs, Ws, r0, c0, acc);
#pragma unroll
    for (int i = 0; i < 4; i++) {
        float2 u0 = unpk(acc[i][0]), u1 = unpk(acc[i][1]);
        *reinterpret_cast<float4*>(g_k + (m0 + r0 + i) * 64 + c0) =
            make_float4(u0.x, u0.y, u1.x, u1.y);
    }
    __syncthreads();
    loadW(Ws, wv, tid);
    __syncthreads();

    gemm64(Fs, Ws, r0, c0, acc);
#pragma unroll
    for (int i = 0; i < 4; i++) {
        float2 u0 = unpk(acc[i][0]), u1 = unpk(acc[i][1]);
        *reinterpret_cast<float4*>(g_v + (m0 + r0 + i) * 64 + c0) =
            make_float4(u0.x, u0.y, u1.x, u1.y);
    }
}

// =========================================================================
// Kernel 2: per block = 4 points x 16 neighbors (64 rows).
//   pos = relu(rel@d1+b)@d2+b ; h = q - k_g + pos ;
//   ap = relu(h@g1+b)@g2+b ; softmax over K per channel ;
//   res = sum_k attn*(v_g+pos) ; out = res@fc2 + b + features
// =========================================================================
__global__ __launch_bounds__(256)
void k2_main(const float* __restrict__ xyz, const float* __restrict__ features,
             const int* __restrict__ knn,
             const float* __restrict__ d1w, const float* __restrict__ d1b,
             const float* __restrict__ d2w, const float* __restrict__ d2b,
             const float* __restrict__ g1w, const float* __restrict__ g1b,
             const float* __restrict__ g2w, const float* __restrict__ g2b,
             const float* __restrict__ fc2w, const float* __restrict__ fc2b,
             float* __restrict__ outRes, float* __restrict__ outAttn) {
    extern __shared__ float sm[];
    float* Wbuf = sm;                 // 64*68
    float* BufA = Wbuf + 64 * 68;     // 64*68
    float* BufB = BufA + 64 * 68;     // 64*68
    float* BufC = BufB + 64 * 68;     // 64*68
    float* qS   = BufC + 64 * 68;     // 4*68
    float* relS = qS + 4 * 68;        // 64*4 (reused as resS[4][64] later)
    float* d1S  = relS + 256;         // 3*64
    float* bS   = d1S + 192;          // 5*64 biases: d1,d2,g1,g2,fc2
    int*   idxS = (int*)(bS + 320);   // 64

    const int tid = threadIdx.x;
    const int pbase = blockIdx.x * 4;
    const int tr = tid >> 4, tc = tid & 15;
    const int r0 = tr * 4, c0 = tc * 4;

    // ---- stage 0: loads ----
    loadW(Wbuf, d2w, tid);
    if (tid < 64) {
        int p = tid >> 4, j = tid & 15;
        int pi = pbase + p;
        int idx = knn[pi * 16 + j];
        int b = pi >> 13;                 // N = 8192
        int grow = (b << 13) + idx;
        idxS[tid] = grow;
#pragma unroll
        for (int c = 0; c < 3; c++)
            relS[tid * 4 + c] = xyz[pi * 3 + c] - xyz[grow * 3 + c];
        bS[tid]       = d1b[tid];
        bS[64 + tid]  = d2b[tid];
        bS[128 + tid] = g1b[tid];
        bS[192 + tid] = g2b[tid];
        bS[256 + tid] = fc2b[tid];
    }
    if (tid < 192) d1S[tid] = d1w[tid];
    {
        int p = tid >> 6, f = tid & 63;
        qS[p * 68 + f] = g_q[(pbase + p) * 64 + f];
    }
    __syncthreads();

    // ---- stage 1: T = relu(rel@d1 + d1b) -> BufA ----
#pragma unroll
    for (int i = 0; i < 4; i++) {
        int r = r0 + i;
        float rx = relS[r * 4 + 0], ry = relS[r * 4 + 1], rz = relS[r * 4 + 2];
#pragma unroll
        for (int jj = 0; jj < 4; jj++) {
            int f = c0 + jj;
            float t = rx * d1S[f] + ry * d1S[64 + f] + rz * d1S[128 + f] + bS[f];
            BufA[r * 68 + f] = fmaxf(t, 0.f);
        }
    }
    __syncthreads();

    // ---- stage 2: pos = BufA @ d2 + d2b (registers) ----
    unsigned long long acc[4][2];
    gemm64(BufA, Wbuf, r0, c0, acc);
    float pos[4][4];
#pragma unroll
    for (int i = 0; i < 4; i++) {
        float2 u0 = unpk(acc[i][0]), u1 = unpk(acc[i][1]);
        pos[i][0] = u0.x + bS[64 + c0 + 0];
        pos[i][1] = u0.y + bS[64 + c0 + 1];
        pos[i][2] = u1.x + bS[64 + c0 + 2];
        pos[i][3] = u1.y + bS[64 + c0 + 3];
    }
    __syncthreads();   // BufA/Wbuf reads done

    // ---- stage 3: h -> BufB, vpos -> BufC; reload Wbuf = g1 ----
#pragma unroll
    for (int i = 0; i < 4; i++) {
        int r = r0 + i;
        int grow = idxS[r];
        int p = r >> 4;
        float4 kv = *reinterpret_cast<const float4*>(g_k + grow * 64 + c0);
        float4 vv = *reinterpret_cast<const float4*>(g_v + grow * 64 + c0);
        float4 qv = *reinterpret_cast<const float4*>(qS + p * 68 + c0);
        float4 h4 = make_float4(qv.x - kv.x + pos[i][0], qv.y - kv.y + pos[i][1],
                                qv.z - kv.z + pos[i][2], qv.w - kv.w + pos[i][3]);
        *reinterpret_cast<float4*>(BufB + r * 68 + c0) = h4;
        float4 vp = make_float4(vv.x + pos[i][0], vv.y + pos[i][1],
                                vv.z + pos[i][2], vv.w + pos[i][3]);
        *reinterpret_cast<float4*>(BufC + r * 68 + c0) = vp;
    }
    loadW(Wbuf, g1w, tid);
    __syncthreads();

    // ---- stage 4: a1 = relu(BufB@g1 + g1b) -> BufA ----
    gemm64(BufB, Wbuf, r0, c0, acc);
#pragma unroll
    for (int i = 0; i < 4; i++) {
        float2 u0 = unpk(acc[i][0]), u1 = unpk(acc[i][1]);
        BufA[(r0 + i) * 68 + c0 + 0] = fmaxf(u0.x + bS[128 + c0 + 0], 0.f);
        BufA[(r0 + i) * 68 + c0 + 1] = fmaxf(u0.y + bS[128 + c0 + 1], 0.f);
        BufA[(r0 + i) * 68 + c0 + 2] = fmaxf(u1.x + bS[128 + c0 + 2], 0.f);
        BufA[(r0 + i) * 68 + c0 + 3] = fmaxf(u1.y + bS[128 + c0 + 3], 0.f);
    }
    __syncthreads();
    loadW(Wbuf, g2w, tid);
    __syncthreads();

    // ---- stage 5: ap = BufA@g2 + g2b -> BufB ----
    gemm64(BufA, Wbuf, r0, c0, acc);
#pragma unroll
    for (int i = 0; i < 4; i++) {
        float2 u0 = unpk(acc[i][0]), u1 = unpk(acc[i][1]);
        BufB[(r0 + i) * 68 + c0 + 0] = u0.x + bS[192 + c0 + 0];
        BufB[(r0 + i) * 68 + c0 + 1] = u0.y + bS[192 + c0 + 1];
        BufB[(r0 + i) * 68 + c0 + 2] = u1.x + bS[192 + c0 + 2];
        BufB[(r0 + i) * 68 + c0 + 3] = u1.y + bS[192 + c0 + 3];
    }
    __syncthreads();
    loadW(Wbuf, fc2w, tid);

    // ---- stage 6: softmax over K per channel; res accumulation ----
    {
        int p = tid >> 6, f = tid & 63;
        int pi = pbase + p;
        float zv[16];
        float m = -3.402823e38f;
#pragma unroll
        for (int j = 0; j < 16; j++) {
            zv[j] = BufB[(p * 16 + j) * 68 + f];
            m = fmaxf(m, zv[j]);
        }
        float s = 0.f;
#pragma unroll
        for (int j = 0; j < 16; j++) {
            float e = __expf((zv[j] - m) * 0.125f);   // /sqrt(64)
            zv[j] = e;
            s += e;
        }
        float inv = 1.f / s;
        float racc = 0.f;
#pragma unroll
        for (int j = 0; j < 16; j++) {
            float a = zv[j] * inv;
            outAttn[(pi * 16 + j) * 64 + f] = a;
            racc += a * BufC[(p * 16 + j) * 68 + f];
        }
        relS[p * 64 + f] = racc;   // reuse relS as resS[4][64]
    }
    __syncthreads();

    // ---- stage 7: out = res@fc2 + fc2b + features ----
    {
        int p = tid >> 6, f = tid & 63;
        int pi = pbase + p;
        float o = bS[256 + f] + features[pi * 64 + f];
#pragma unroll 16
        for (int i = 0; i < 64; i++)
            o += relS[p * 64 + i] * Wbuf[i * 68 + f];
        outRes[pi * 64 + f] = o;
    }
}

// =========================================================================
extern "C" void kernel_launch(void* const* d_in, const int* in_sizes, int n_in,
                              void* d_out, int out_size) {
    const float* xyz      = (const float*)d_in[0];
    const float* features = (const float*)d_in[1];
    const int*   knn      = (const int*)d_in[2];
    const float* fc1w = (const float*)d_in[3];
    const float* fc1b = (const float*)d_in[4];
    const float* fc2w = (const float*)d_in[5];
    const float* fc2b = (const float*)d_in[6];
    const float* d1w  = (const float*)d_in[7];
    const float* d1b  = (const float*)d_in[8];
    const float* d2w  = (const float*)d_in[9];
    const float* d2b  = (const float*)d_in[10];
    const float* g1w  = (const float*)d_in[11];
    const float* g1b  = (const float*)d_in[12];
    const float* g2w  = (const float*)d_in[13];
    const float* g2b  = (const float*)d_in[14];
    const float* wq   = (const float*)d_in[15];
    const float* wk   = (const float*)d_in[16];
    const float* wv   = (const float*)d_in[17];

    float* outRes  = (float*)d_out;
    float* outAttn = outRes + (size_t)M_ * D_;   // tuple order: (res, attn)

    const int smem2 = 18512 * 4;  // 74048 B
    cudaFuncSetAttribute(k2_main, cudaFuncAttributeMaxDynamicSharedMemorySize, smem2);

    k1_proj<<<M_ / 64, 256>>>(features, fc1w, fc1b, wq, wk, wv);
    k2_main<<<M_ / 4, 256, smem2>>>(xyz, features, knn,
                                    d1w, d1b, d2w, d2b,
                                    g1w, g1b, g2w, g2b,
                                    fc2w, fc2b, outRes, outAttn);
}